// round 14
// baseline (speedup 1.0000x reference)
#include <cuda_runtime.h>

#define IMG_W 4096
#define IMG_H 4096
#define OUT_W 4097
#define OUT_H 4097
#define TW    64      // tile width  (output cols per block)
#define TH    32      // tile height (output rows per block)
#define HR    35      // hist rows   (TH + 3)
#define HC    67      // hist cols   (TW + 3)
#define IR    37      // input rows  (HR + 2)
#define IC    69      // input cols  (HC + 2)
#define INP   70      // input row stride (words)
#define HPAD  69      // s_pk row stride (odd -> conflict-free)

#define SMEM_RS    (2 * HR * TW * 16)          // 71680 B
#define SMEM_TOTAL (SMEM_RS + HR * HPAD * 4)   // 81340 B

__device__ __forceinline__ float4 f4add(float4 a, float4 b) {
    return make_float4(a.x + b.x, a.y + b.y, a.z + b.z, a.w + b.w);
}
__device__ __forceinline__ float4 f4addsub(float4 a, float4 p, float4 m) {
    return make_float4(a.x + p.x - m.x, a.y + p.y - m.y,
                       a.z + p.z - m.z, a.w + p.w - m.w);
}

// Sobel gradients -> packed (mag & ~7) | octant-bin
__device__ __forceinline__ unsigned int pack_pix(float dx, float dy)
{
    unsigned int sx = __float_as_uint(dx) >> 31;
    unsigned int sy = __float_as_uint(dy) >> 31;
    unsigned int tb = (fabsf(dy) > fabsf(dx)) ? 1u : 0u;
    unsigned int ex = sx ^ sy;
    unsigned int bi = (sy << 2) | (ex << 1) | (ex ^ tb);
    float m2  = fmaf(dx, dx, dy * dy);
    float mag = m2 * rsqrtf(fmaxf(m2, 1e-35f));
    return (__float_as_uint(mag) & 0xFFFFFFF8u) | bi;
}

__global__ __launch_bounds__(512, 2)
void sift_fused_kernel(const float* __restrict__ x, float* __restrict__ out)
{
    extern __shared__ char smem[];
    float4*       rsb  = (float4*)smem;                       // [2][HR][TW]
    unsigned int (*s_pk)[HPAD] =
        (unsigned int (*)[HPAD])(smem + SMEM_RS);             // [HR][HPAD]
    float*        s_in = (float*)smem;  // [IR][INP] = 10360 B, dead after stage 2

    const int X0   = blockIdx.x * TW;
    const int Y0   = blockIdx.y * TH;
    const int tid  = threadIdx.x;
    const int lane = tid & 31;
    const int wrow = tid >> 5;    // 0..15

    const bool interior =
        blockIdx.x >= 1 && blockIdx.x <= 62 &&
        blockIdx.y >= 1 && blockIdx.y <= 126;

    // ---- Stage 1: load input tile (origin Y0-3, X0-3) ----
    if (interior) {
        const float* src = x + (size_t)(Y0 - 3) * IMG_W + (X0 - 3);
        for (int r = wrow; r < IR; r += 16) {
            const float* row = src + (size_t)r * IMG_W;
            s_in[r * INP + lane]      = row[lane];
            s_in[r * INP + 32 + lane] = row[32 + lane];
            if (lane < IC - 64)
                s_in[r * INP + 64 + lane] = row[64 + lane];
        }
    } else {
        for (int r = wrow; r < IR; r += 16) {
            int  gy    = Y0 - 3 + r;
            bool rowok = (gy >= 0) && (gy < IMG_H);
            const float* row = x + (size_t)gy * IMG_W;
            int gx0 = X0 - 3 + lane;
            s_in[r * INP + lane] =
                (rowok && gx0 >= 0 && gx0 < IMG_W) ? row[gx0] : 0.0f;
            int gx1 = gx0 + 32;
            s_in[r * INP + 32 + lane] =
                (rowok && gx1 >= 0 && gx1 < IMG_W) ? row[gx1] : 0.0f;
            if (lane < IC - 64) {
                int gx2 = gx0 + 64;
                s_in[r * INP + 64 + lane] =
                    (rowok && gx2 >= 0 && gx2 < IMG_W) ? row[gx2] : 0.0f;
            }
        }
    }
    __syncthreads();

    // ---- Stage 2: flat per-pixel Sobel + octant bin + packed store ----
    #pragma unroll
    for (int it = 0; it < 5; ++it) {
        int e = tid + 512 * it;
        if (e < HR * HC) {
            int h = e / HC, w = e - h * HC;
            const float* c = s_in + h * INP + w;
            float a00 = c[0],       a01 = c[1],           a02 = c[2];
            float a10 = c[INP],                            a12 = c[INP + 2];
            float a20 = c[2*INP],   a21 = c[2*INP + 1],   a22 = c[2*INP + 2];

            float dx = (a02 - a00) + 2.0f * (a12 - a10) + (a22 - a20);
            float dy = (a20 - a00) + 2.0f * (a21 - a01) + (a22 - a02);

            unsigned int bits = pack_pix(dx, dy);

            if (!interior) {
                int gy = Y0 - 2 + h;
                int gx = X0 - 2 + w;
                if (!(gy >= 0 && gy < IMG_H && gx >= 0 && gx < IMG_W)) bits = 0u;
            }
            s_pk[h][w] = bits;
        }
    }
    __syncthreads();

    // ---- Stage 3: horizontal 4-tap row sums with one-hot scatter ----
    #pragma unroll
    for (int it = 0; it < 5; ++it) {
        int e = tid + 512 * it;
        if (e < HR * TW) {
            int h  = e >> 6;
            int ox = e & 63;
            float a0 = 0.f, a1 = 0.f, a2 = 0.f, a3 = 0.f;
            float a4 = 0.f, a5 = 0.f, a6 = 0.f, a7 = 0.f;
            #pragma unroll
            for (int k = 0; k < 4; k++) {
                unsigned int u = s_pk[h][ox + k];
                unsigned int i = u & 7u;
                float m = __uint_as_float(u);   // idx bits: <=2^-21 rel noise
                if (i == 0u) a0 += m;
                if (i == 1u) a1 += m;
                if (i == 2u) a2 += m;
                if (i == 3u) a3 += m;
                if (i == 4u) a4 += m;
                if (i == 5u) a5 += m;
                if (i == 6u) a6 += m;
                if (i == 7u) a7 += m;
            }
            rsb[(0 * HR + h) * TW + ox] = make_float4(a0, a1, a2, a3);
            rsb[(1 * HR + h) * TW + ox] = make_float4(a4, a5, a6, a7);
        }
    }
    __syncthreads();

    // ---- Stage 4: vertical 4-tap sliding sum + store 8 channels ----
    // warp wrow: x-half = wrow&1, row group = wrow>>1 (4 rows each)
    const int    xh    = (wrow & 1) * 32 + lane;   // 0..63
    const int    oy0   = (wrow >> 1) * 4;          // 0..28
    const int    gx    = X0 + xh;
    const size_t plane = (size_t)OUT_H * OUT_W;

    const float4* c0 = rsb + (0 * HR) * TW + xh;
    const float4* c1 = rsb + (1 * HR) * TW + xh;

    float4 lo = f4add(f4add(c0[(oy0    ) * TW], c0[(oy0 + 1) * TW]),
                      f4add(c0[(oy0 + 2) * TW], c0[(oy0 + 3) * TW]));
    float4 hi = f4add(f4add(c1[(oy0    ) * TW], c1[(oy0 + 1) * TW]),
                      f4add(c1[(oy0 + 2) * TW], c1[(oy0 + 3) * TW]));

    #pragma unroll
    for (int r = 0; r < 4; r++) {
        if (r > 0) {
            lo = f4addsub(lo, c0[(oy0 + r + 3) * TW], c0[(oy0 + r - 1) * TW]);
            hi = f4addsub(hi, c1[(oy0 + r + 3) * TW], c1[(oy0 + r - 1) * TW]);
        }
        int gy = Y0 + oy0 + r;
        if (gy < OUT_H && gx < OUT_W) {
            size_t base = (size_t)gy * OUT_W + gx;
            out[0 * plane + base] = lo.x;
            out[1 * plane + base] = lo.y;
            out[2 * plane + base] = lo.z;
            out[3 * plane + base] = lo.w;
            out[4 * plane + base] = hi.x;
            out[5 * plane + base] = hi.y;
            out[6 * plane + base] = hi.z;
            out[7 * plane + base] = hi.w;
        }
    }
}

extern "C" void kernel_launch(void* const* d_in, const int* in_sizes, int n_in,
                              void* d_out, int out_size)
{
    const float* x   = (const float*)d_in[0];
    float*       out = (float*)d_out;
    cudaFuncSetAttribute(sift_fused_kernel,
                         cudaFuncAttributeMaxDynamicSharedMemorySize, SMEM_TOTAL);
    dim3 grid((OUT_W + TW - 1) / TW, (OUT_H + TH - 1) / TH);   // 65 x 129
    sift_fused_kernel<<<grid, 512, SMEM_TOTAL>>>(x, out);
}